// round 7
// baseline (speedup 1.0000x reference)
#include <cuda_runtime.h>
#include <cuda_bf16.h>
#include <math.h>

// ---------------- Problem constants ----------------
// B=32, C_IN=1, L=16384, D=64, K=512
// out: [loss(1), recon(32*16385), perplexity(1), indices(131072)] = 655394 floats

#define NROWS   131072
#define IDX_OFF 524322
#define PERP_OFF 524321

typedef unsigned long long ull;

// packed f32x2 helpers (decoder + VQ-approx screening only; exact paths stay scalar)
#define FMA2(d,a,b,c) asm("fma.rn.f32x2 %0, %1, %2, %3;" : "=l"(d) : "l"(a), "l"(b), "l"(c))
__device__ __forceinline__ ull pk2(float v) {
    ull p; unsigned u = __float_as_uint(v);
    asm("mov.b64 %0, {%1, %1};" : "=l"(p) : "r"(u));
    return p;
}
__device__ __forceinline__ void unpk2(ull p, float& lo, float& hi) {
    unsigned a, b;
    asm("mov.b64 {%0, %1}, %2;" : "=r"(a), "=r"(b) : "l"(p));
    lo = __uint_as_float(a); hi = __uint_as_float(b);
}

// ---------------- Scratch (device globals; no allocation) ----------------
__device__ __align__(16) float g_a2[32*4096*64];
__device__ __align__(16) float g_a3[32*4096*128];
__device__ __align__(16) float g_z [NROWS*64];
__device__ __align__(16) float g_d1[32*4096*128];
__device__ __align__(16) float g_d2[32*4096*64];
__device__ __align__(16) float g_d3[32*8192*32];
__device__ __align__(16) float g_wt2[4*32*64];
__device__ __align__(16) float g_wt3[3*64*128];
__device__ __align__(16) float g_wt4[128*64];
__device__ __align__(16) float g_wtd2[3*128*64];
__device__ __align__(16) float g_wtd3f[3*64*64];
__device__ __align__(16) float g_wtd4[4*32];
__device__ __align__(16) float g_b3f[64];
__device__ float g_partial[512];
__device__ int   g_fidx[NROWS];
__device__ int   g_flaglist[NROWS];
__device__ int   g_nflag;
__device__ int   g_counts[512];

// ---------------- Weight re-layout: wt[(j*CIN+ci)*COUT + co] ----------------
__global__ void transform_kernel(const float* __restrict__ ew2, const float* __restrict__ ew3,
                                 const float* __restrict__ ew4,
                                 const float* __restrict__ dw2,
                                 const float* __restrict__ dw3, const float* __restrict__ db3,
                                 const float* __restrict__ dw4,
                                 float* __restrict__ wt2, float* __restrict__ wt3,
                                 float* __restrict__ wt4,
                                 float* __restrict__ wtd2,
                                 float* __restrict__ wtd3f, float* __restrict__ b3f,
                                 float* __restrict__ wtd4)
{
    int i = blockIdx.x * blockDim.x + threadIdx.x;
    if (i < 8192)  { int j=i/2048, ci=(i/64)%32, co=i%64;   wt2[i]  = ew2[(co*32+ci)*4 + j]; }
    if (i < 24576) { int j=i/8192, ci=(i/128)%64, co=i%128; wt3[i]  = ew3[(co*64+ci)*3 + j]; }
    if (i < 8192)  { int ci=i/64,  co=i%64;                 wt4[i]  = ew4[co*128 + ci]; }
    if (i < 24576) { int j=i/8192, ci=(i/64)%128, co=i%64;  wtd2[i] = dw2[(ci*64+co)*3 + (2-j)]; }
    if (i < 12288) {
        int j=i/4096, ci=(i/64)%64, cop=i%64;
        int phase = cop >> 5, co = cop & 31;
        int tap = -1;
        if (phase == 0) { if (j == 0) tap = 3; else if (j == 1) tap = 1; }
        else            { if (j == 1) tap = 2; else if (j == 2) tap = 0; }
        wtd3f[i] = (tap >= 0) ? dw3[(ci*32+co)*4 + tap] : 0.f;
    }
    if (i < 128)   { int j=i/32,  ci=i%32;                  wtd4[i] = dw4[ci*4 + j]; }
    if (i < 64)    { b3f[i] = db3[i & 31]; }
}

__global__ void zero_counts_kernel(int* __restrict__ counts, int* __restrict__ nflag)
{
    counts[threadIdx.x] = 0;
    if (threadIdx.x == 0) *nflag = 0;
}

// ---------------- scalar smem-staged conv (index path — exact R4/R6 FMA chain) ----------------
template<int CIN, int COUT, int K, int S, int P, bool RELU, int TT, int MINB>
__global__ __launch_bounds__(256, MINB) void convSs(const float* __restrict__ in,
                                                    const float* __restrict__ wt,
                                                    const float* __restrict__ bias,
                                                    float* __restrict__ out,
                                                    int Lin, int Lout)
{
    constexpr int C4  = CIN / 4;
    constexpr int CO4 = COUT / 4;
    constexpr int TY  = CO4;
    constexpr int TX  = 256 / TY;
    constexpr int POS  = TX * TT;
    constexpr int PB   = (POS - 1) * S + K;
    constexpr int I4   = PB * C4;
    constexpr int SPAN = (TT - 1) * S + K;

    extern __shared__ float4 is[];
    int tid = threadIdx.x;
    int blockPos = blockIdx.x * POS;
    int b   = blockPos / Lout;
    int t0b = blockPos % Lout;
    int p0b = t0b * S - P;
    const float4* in4 = reinterpret_cast<const float4*>(in);
    for (int i = tid; i < I4; i += 256) {
        int pl = i / C4, c4 = i % C4;
        int p = p0b + pl;
        is[i] = (p >= 0 && p < Lin) ? in4[(b*Lin + p)*C4 + c4]
                                    : make_float4(0.f, 0.f, 0.f, 0.f);
    }
    __syncthreads();

    int ty = tid % TY, tx = tid / TY, tloc = tx * TT;
    const float4* wt4 = reinterpret_cast<const float4*>(wt);

    float4 acc[TT];
    #pragma unroll
    for (int tt = 0; tt < TT; tt++) acc[tt] = make_float4(0.f, 0.f, 0.f, 0.f);

    for (int c4 = 0; c4 < C4; c4++) {
        float4 iv[SPAN];
        #pragma unroll
        for (int s = 0; s < SPAN; s++) iv[s] = is[(tloc*S + s)*C4 + c4];
        #pragma unroll
        for (int j = 0; j < K; j++) {
            float4 w0 = __ldg(&wt4[(j*CIN + c4*4 + 0)*CO4 + ty]);
            float4 w1 = __ldg(&wt4[(j*CIN + c4*4 + 1)*CO4 + ty]);
            float4 w2 = __ldg(&wt4[(j*CIN + c4*4 + 2)*CO4 + ty]);
            float4 w3 = __ldg(&wt4[(j*CIN + c4*4 + 3)*CO4 + ty]);
            #pragma unroll
            for (int tt = 0; tt < TT; tt++) {
                float4 xv = iv[tt*S + j];
                acc[tt].x += w0.x*xv.x + w1.x*xv.y + w2.x*xv.z + w3.x*xv.w;
                acc[tt].y += w0.y*xv.x + w1.y*xv.y + w2.y*xv.z + w3.y*xv.w;
                acc[tt].z += w0.z*xv.x + w1.z*xv.y + w2.z*xv.z + w3.z*xv.w;
                acc[tt].w += w0.w*xv.x + w1.w*xv.y + w2.w*xv.z + w3.w*xv.w;
            }
        }
    }

    float4 bv = reinterpret_cast<const float4*>(bias)[ty];
    float4* out4 = reinterpret_cast<float4*>(out);
    #pragma unroll
    for (int tt = 0; tt < TT; tt++) {
        float4 v;
        v.x = acc[tt].x + bv.x; v.y = acc[tt].y + bv.y;
        v.z = acc[tt].z + bv.z; v.w = acc[tt].w + bv.w;
        if (RELU) {
            v.x = fmaxf(v.x, 0.f); v.y = fmaxf(v.y, 0.f);
            v.z = fmaxf(v.z, 0.f); v.w = fmaxf(v.w, 0.f);
        }
        out4[(b*Lout + t0b + tloc + tt)*CO4 + ty] = v;
    }
}

// ---------------- f32x2 smem-staged conv (DECODER ONLY) ----------------
template<int CIN, int COUT, int K, int S, int P, bool RELU, int TT>
__global__ __launch_bounds__(256) void convS2(const float* __restrict__ in,
                                              const float* __restrict__ wt,
                                              const float* __restrict__ bias,
                                              float* __restrict__ out,
                                              int Lin, int Lout)
{
    constexpr int C4  = CIN / 4;
    constexpr int CO4 = COUT / 4;
    constexpr int TY  = CO4;
    constexpr int TX  = 256 / TY;
    constexpr int POS  = TX * TT;
    constexpr int PB   = (POS - 1) * S + K;
    constexpr int I4   = PB * C4;
    constexpr int SPAN = (TT - 1) * S + K;

    extern __shared__ float4 is[];
    int tid = threadIdx.x;
    int blockPos = blockIdx.x * POS;
    int b   = blockPos / Lout;
    int t0b = blockPos % Lout;
    int p0b = t0b * S - P;
    const float4* in4 = reinterpret_cast<const float4*>(in);
    for (int i = tid; i < I4; i += 256) {
        int pl = i / C4, c4 = i % C4;
        int p = p0b + pl;
        is[i] = (p >= 0 && p < Lin) ? in4[(b*Lin + p)*C4 + c4]
                                    : make_float4(0.f, 0.f, 0.f, 0.f);
    }
    __syncthreads();

    int ty = tid % TY, tx = tid / TY, tloc = tx * TT;
    const float4* wt4 = reinterpret_cast<const float4*>(wt);

    ull a01[TT], a23[TT];
    #pragma unroll
    for (int t = 0; t < TT; t++) { a01[t] = 0ull; a23[t] = 0ull; }

    for (int c4 = 0; c4 < C4; c4++) {
        float4 iv[SPAN];
        #pragma unroll
        for (int s = 0; s < SPAN; s++) iv[s] = is[(tloc*S + s)*C4 + c4];
        #pragma unroll
        for (int j = 0; j < K; j++) {
            float4 w0 = __ldg(&wt4[(j*CIN + c4*4 + 0)*CO4 + ty]);
            float4 w1 = __ldg(&wt4[(j*CIN + c4*4 + 1)*CO4 + ty]);
            float4 w2 = __ldg(&wt4[(j*CIN + c4*4 + 2)*CO4 + ty]);
            float4 w3 = __ldg(&wt4[(j*CIN + c4*4 + 3)*CO4 + ty]);
            ulonglong2 p0 = *reinterpret_cast<ulonglong2*>(&w0);
            ulonglong2 p1 = *reinterpret_cast<ulonglong2*>(&w1);
            ulonglong2 p2 = *reinterpret_cast<ulonglong2*>(&w2);
            ulonglong2 p3 = *reinterpret_cast<ulonglong2*>(&w3);
            #pragma unroll
            for (int t = 0; t < TT; t++) {
                float4 xv = iv[t*S + j];
                ull d;
                d = pk2(xv.x); FMA2(a01[t], p0.x, d, a01[t]); FMA2(a23[t], p0.y, d, a23[t]);
                d = pk2(xv.y); FMA2(a01[t], p1.x, d, a01[t]); FMA2(a23[t], p1.y, d, a23[t]);
                d = pk2(xv.z); FMA2(a01[t], p2.x, d, a01[t]); FMA2(a23[t], p2.y, d, a23[t]);
                d = pk2(xv.w); FMA2(a01[t], p3.x, d, a01[t]); FMA2(a23[t], p3.y, d, a23[t]);
            }
        }
    }

    float4 bv = reinterpret_cast<const float4*>(bias)[ty];
    float4* out4 = reinterpret_cast<float4*>(out);
    #pragma unroll
    for (int t = 0; t < TT; t++) {
        float x0, x1, x2, x3;
        unpk2(a01[t], x0, x1);
        unpk2(a23[t], x2, x3);
        float4 v;
        v.x = x0 + bv.x; v.y = x1 + bv.y; v.z = x2 + bv.z; v.w = x3 + bv.w;
        if (RELU) {
            v.x = fmaxf(v.x, 0.f); v.y = fmaxf(v.y, 0.f);
            v.z = fmaxf(v.z, 0.f); v.w = fmaxf(v.w, 0.f);
        }
        out4[(b*Lout + t0b + tloc + t)*CO4 + ty] = v;
    }
}

// ---------------- fused enc1 + enc2 (scalar — index path) ----------------
__global__ __launch_bounds__(256) void enc12_kernel(const float* __restrict__ x,
                                                    const float* __restrict__ w1,
                                                    const float* __restrict__ b1,
                                                    const float* __restrict__ wt2,
                                                    const float* __restrict__ b2,
                                                    float* __restrict__ out)
{
    constexpr int TT = 4, TY = 16, POS = 64, PB = 130, C4 = 8, CO4 = 16, K = 4, S = 2, SPAN = 10;
    __shared__ float4 is[PB*C4];
    __shared__ float  xs[264];
    __shared__ float  w1s[128];
    __shared__ float  b1s[32];

    int tid = threadIdx.x;
    int blockPos = blockIdx.x * POS;
    int b   = blockPos >> 12;
    int t0b = blockPos & 4095;
    int p0b = t0b*2 - 1;
    int xstart = 2*p0b - 1;

    if (tid < 128) w1s[tid] = w1[tid];
    if (tid < 32)  b1s[tid] = b1[tid];
    for (int i = tid; i < 262; i += 256) {
        int xi = xstart + i;
        xs[i] = (xi >= 0 && xi < 16384) ? x[b*16384 + xi] : 0.f;
    }
    __syncthreads();

    for (int i = tid; i < PB*C4; i += 256) {
        int pl = i >> 3, c4 = i & 7;
        int pos = p0b + pl;
        float4 v = make_float4(0.f, 0.f, 0.f, 0.f);
        if (pos >= 0 && pos < 8192) {
            float r[4];
            #pragma unroll
            for (int ch = 0; ch < 4; ch++) {
                int co = c4*4 + ch;
                float acc = b1s[co];
                #pragma unroll
                for (int j = 0; j < 4; j++) acc += w1s[co*4 + j] * xs[2*pl + j];
                r[ch] = fmaxf(acc, 0.f);
            }
            v = make_float4(r[0], r[1], r[2], r[3]);
        }
        is[i] = v;
    }
    __syncthreads();

    int ty = tid % TY, tx = tid / TY, tloc = tx * TT;
    const float4* wt4 = reinterpret_cast<const float4*>(wt2);

    float4 acc[TT];
    #pragma unroll
    for (int t = 0; t < TT; t++) acc[t] = make_float4(0.f, 0.f, 0.f, 0.f);

    for (int c4 = 0; c4 < C4; c4++) {
        float4 iv[SPAN];
        #pragma unroll
        for (int s = 0; s < SPAN; s++) iv[s] = is[(tloc*S + s)*C4 + c4];
        #pragma unroll
        for (int j = 0; j < K; j++) {
            float4 w0 = __ldg(&wt4[(j*32 + c4*4 + 0)*CO4 + ty]);
            float4 w1v = __ldg(&wt4[(j*32 + c4*4 + 1)*CO4 + ty]);
            float4 w2 = __ldg(&wt4[(j*32 + c4*4 + 2)*CO4 + ty]);
            float4 w3 = __ldg(&wt4[(j*32 + c4*4 + 3)*CO4 + ty]);
            #pragma unroll
            for (int t = 0; t < TT; t++) {
                float4 xv = iv[t*S + j];
                acc[t].x += w0.x*xv.x + w1v.x*xv.y + w2.x*xv.z + w3.x*xv.w;
                acc[t].y += w0.y*xv.x + w1v.y*xv.y + w2.y*xv.z + w3.y*xv.w;
                acc[t].z += w0.z*xv.x + w1v.z*xv.y + w2.z*xv.z + w3.z*xv.w;
                acc[t].w += w0.w*xv.x + w1v.w*xv.y + w2.w*xv.z + w3.w*xv.w;
            }
        }
    }

    float4 bv = reinterpret_cast<const float4*>(b2)[ty];
    float4* out4 = reinterpret_cast<float4*>(out);
    #pragma unroll
    for (int t = 0; t < TT; t++) {
        float4 v;
        v.x = fmaxf(acc[t].x + bv.x, 0.f); v.y = fmaxf(acc[t].y + bv.y, 0.f);
        v.z = fmaxf(acc[t].z + bv.z, 0.f); v.w = fmaxf(acc[t].w + bv.w, 0.f);
        out4[(b*4096 + t0b + tloc + t)*CO4 + ty] = v;
    }
}

// ---------------- VQ pass 1: FFMA2 approx scan + margin screening ----------------
// Distances are quantized to ulp(~64)=7.6e-6 by the x2+ek2 term. FFMA2 reassociation
// perturbs acc by ~1e-8 -> distance moves by at most one grid step. If the top-2
// margin exceeds MARGIN (>2 steps), approx winner == exact winner (ties included).
// Otherwise the row is flagged for exact re-scan.
#define VQ_MARGIN 2e-5f
__global__ __launch_bounds__(256) void vq_approx_kernel(const float* __restrict__ z,
                                                        const float* __restrict__ emb,
                                                        int* __restrict__ fidx,
                                                        int* __restrict__ flaglist,
                                                        int* __restrict__ nflag)
{
    __shared__ float4 es[2048];
    __shared__ float  ek2s[128];

    int tid = threadIdx.x;
    int row = blockIdx.x * 256 + tid;
    const float4* z4 = reinterpret_cast<const float4*>(z);
    const float4* e4 = reinterpret_cast<const float4*>(emb);

    float4 zv[16];
    #pragma unroll
    for (int dv = 0; dv < 16; dv++) zv[dv] = __ldg(&z4[row*16 + dv]);

    float x2 = 0.f;
    #pragma unroll
    for (int dv = 0; dv < 16; dv++) {
        float4 v = zv[dv];
        x2 += v.x*v.x + v.y*v.y + v.z*v.z + v.w*v.w;
    }
    const ulonglong2* zp = reinterpret_cast<const ulonglong2*>(zv);

    float m1 = 3.4e38f, m2 = 3.4e38f;
    int i1 = 0;
    for (int ch = 0; ch < 4; ch++) {
        for (int i = tid; i < 2048; i += 256) es[i] = e4[ch*2048 + i];
        __syncthreads();
        if (tid < 128) {
            float s = 0.f;
            #pragma unroll
            for (int dv = 0; dv < 16; dv++) {
                float4 v = es[tid*16 + dv];
                s += v.x*v.x + v.y*v.y + v.z*v.z + v.w*v.w;
            }
            ek2s[tid] = s;
        }
        __syncthreads();
        const ulonglong2* ep = reinterpret_cast<const ulonglong2*>(es);
        for (int c = 0; c < 128; c++) {
            ull acc = 0ull;
            #pragma unroll
            for (int dv = 0; dv < 16; dv++) {
                ulonglong2 e = ep[c*16 + dv];
                FMA2(acc, e.x, zp[dv].x, acc);
                FMA2(acc, e.y, zp[dv].y, acc);
            }
            float l, h;
            unpk2(acc, l, h);
            float a = l + h;
            float t = x2 + ek2s[c];
            float d = t - 2.f*a;
            int code = ch*128 + c;
            if (d < m1) { m2 = m1; m1 = d; i1 = code; }
            else if (d < m2) { m2 = d; }
        }
        __syncthreads();
    }

    fidx[row] = i1;
    if (m2 - m1 <= VQ_MARGIN) {
        int slot = atomicAdd(nflag, 1);
        flaglist[slot] = row;
    }
}

// ---------------- VQ pass 2: exact re-scan of flagged rows (R6 scalar chains) ----------------
__global__ void vq_fallback_kernel(const float* __restrict__ z, const float* __restrict__ emb,
                                   const int* __restrict__ flaglist, const int* __restrict__ nflag,
                                   int* __restrict__ fidx)
{
    int n = *nflag;
    int gwarp = (blockIdx.x * blockDim.x + threadIdx.x) >> 5;
    int lane  = threadIdx.x & 31;
    int nwarps = (gridDim.x * blockDim.x) >> 5;
    const float4* z4 = reinterpret_cast<const float4*>(z);
    const float4* e4 = reinterpret_cast<const float4*>(emb);

    for (int i = gwarp; i < n; i += nwarps) {
        int row = flaglist[i];
        float4 zv[16];
        #pragma unroll
        for (int dv = 0; dv < 16; dv++) zv[dv] = __ldg(&z4[row*16 + dv]);
        float x2 = 0.f;
        #pragma unroll
        for (int dv = 0; dv < 16; dv++) {
            float4 v = zv[dv];
            x2 += v.x*v.x + v.y*v.y + v.z*v.z + v.w*v.w;
        }
        float best = 3.4e38f;
        int bidx = 0;
        // contiguous 16-code stripe per lane: within-lane ascending + idx tie-break
        // across lanes == global lowest-index tie-break
        for (int k = 0; k < 16; k++) {
            int code = lane*16 + k;
            float s = 0.f;
            float acc = 0.f;
            #pragma unroll
            for (int dv = 0; dv < 16; dv++) {
                float4 e = __ldg(&e4[code*16 + dv]);
                s   += e.x*e.x + e.y*e.y + e.z*e.z + e.w*e.w;
                acc += e.x*zv[dv].x + e.y*zv[dv].y + e.z*zv[dv].z + e.w*zv[dv].w;
            }
            float t = x2 + s;
            float d = t - 2.f*acc;
            if (d < best) { best = d; bidx = code; }
        }
        #pragma unroll
        for (int off = 16; off > 0; off >>= 1) {
            float ov = __shfl_down_sync(0xffffffffu, best, off);
            int   oi = __shfl_down_sync(0xffffffffu, bidx, off);
            if (ov < best || (ov == best && oi < bidx)) { best = ov; bidx = oi; }
        }
        if (lane == 0) fidx[row] = bidx;
    }
}

// ---------------- VQ pass 3: indices out + histogram + loss partials ----------------
__global__ __launch_bounds__(256) void vq_loss_kernel(const float* __restrict__ z,
                                                      const float* __restrict__ emb,
                                                      const int* __restrict__ fidx,
                                                      float* __restrict__ out,
                                                      float* __restrict__ partial,
                                                      int* __restrict__ counts)
{
    __shared__ float red[256];
    int tid = threadIdx.x;
    int row = blockIdx.x * 256 + tid;
    const float4* z4 = reinterpret_cast<const float4*>(z);
    const float4* e4 = reinterpret_cast<const float4*>(emb);

    int idx = fidx[row];
    out[IDX_OFF + row] = (float)idx;
    atomicAdd(&counts[idx], 1);

    float ls = 0.f;
    #pragma unroll
    for (int dv = 0; dv < 16; dv++) {
        float4 ev = __ldg(&e4[idx*16 + dv]);
        float4 q  = __ldg(&z4[row*16 + dv]);
        float dx = ev.x - q.x, dy = ev.y - q.y, dz = ev.z - q.z, dw = ev.w - q.w;
        ls += dx*dx + dy*dy + dz*dz + dw*dw;
    }
    red[tid] = ls;
    __syncthreads();
    for (int s = 128; s > 0; s >>= 1) {
        if (tid < s) red[tid] += red[tid + s];
        __syncthreads();
    }
    if (tid == 0) partial[blockIdx.x] = red[0];
}

// ---------------- dcv1 with gather: q = emb[fidx[row]], conv k=1 (f32x2 ok) ----------------
template<int CIN, int COUT>
__global__ __launch_bounds__(256) void convG1(const float* __restrict__ emb,
                                              const int* __restrict__ fidx,
                                              const float* __restrict__ wt,
                                              const float* __restrict__ bias,
                                              float* __restrict__ out)
{
    constexpr int C4 = CIN/4, CO4 = COUT/4, TY = CO4, TX = 256/TY, TT = 4, POS = TX*TT;
    extern __shared__ float4 is[];
    int tid = threadIdx.x;
    int blockPos = blockIdx.x * POS;
    const float4* e4 = reinterpret_cast<const float4*>(emb);
    for (int i = tid; i < POS*C4; i += 256) {
        int pl = i / C4, c4 = i % C4;
        is[i] = e4[fidx[blockPos + pl]*C4 + c4];
    }
    __syncthreads();

    int ty = tid % TY, tx = tid / TY, tloc = tx * TT;
    const float4* wt4 = reinterpret_cast<const float4*>(wt);

    ull a01[TT], a23[TT];
    #pragma unroll
    for (int t = 0; t < TT; t++) { a01[t] = 0ull; a23[t] = 0ull; }

    for (int c4 = 0; c4 < C4; c4++) {
        float4 iv[TT];
        #pragma unroll
        for (int t = 0; t < TT; t++) iv[t] = is[(tloc + t)*C4 + c4];
        float4 w0 = __ldg(&wt4[(c4*4 + 0)*CO4 + ty]);
        float4 w1 = __ldg(&wt4[(c4*4 + 1)*CO4 + ty]);
        float4 w2 = __ldg(&wt4[(c4*4 + 2)*CO4 + ty]);
        float4 w3 = __ldg(&wt4[(c4*4 + 3)*CO4 + ty]);
        ulonglong2 p0 = *reinterpret_cast<ulonglong2*>(&w0);
        ulonglong2 p1 = *reinterpret_cast<ulonglong2*>(&w1);
        ulonglong2 p2 = *reinterpret_cast<ulonglong2*>(&w2);
        ulonglong2 p3 = *reinterpret_cast<ulonglong2*>(&w3);
        #pragma unroll
        for (int t = 0; t < TT; t++) {
            float4 xv = iv[t];
            ull d;
            d = pk2(xv.x); FMA2(a01[t], p0.x, d, a01[t]); FMA2(a23[t], p0.y, d, a23[t]);
            d = pk2(xv.y); FMA2(a01[t], p1.x, d, a01[t]); FMA2(a23[t], p1.y, d, a23[t]);
            d = pk2(xv.z); FMA2(a01[t], p2.x, d, a01[t]); FMA2(a23[t], p2.y, d, a23[t]);
            d = pk2(xv.w); FMA2(a01[t], p3.x, d, a01[t]); FMA2(a23[t], p3.y, d, a23[t]);
        }
    }

    float4 bv = reinterpret_cast<const float4*>(bias)[ty];
    float4* out4 = reinterpret_cast<float4*>(out);
    #pragma unroll
    for (int t = 0; t < TT; t++) {
        float x0, x1, x2, x3;
        unpk2(a01[t], x0, x1);
        unpk2(a23[t], x2, x3);
        float4 v;
        v.x = fmaxf(x0 + bv.x, 0.f); v.y = fmaxf(x1 + bv.y, 0.f);
        v.z = fmaxf(x2 + bv.z, 0.f); v.w = fmaxf(x3 + bv.w, 0.f);
        out4[(blockPos + tloc + t)*CO4 + ty] = v;
    }
}

// ---------------- finalize: loss + perplexity ----------------
__global__ void finalize_kernel(const float* __restrict__ partial, const int* __restrict__ counts,
                                float* __restrict__ out)
{
    __shared__ double red[512];
    int tid = threadIdx.x;
    double s = 0.0;
    for (int i = tid; i < 512; i += 512) s += (double)partial[i];
    red[tid] = s;
    __syncthreads();
    for (int st = 256; st > 0; st >>= 1) {
        if (tid < st) red[tid] += red[tid + st];
        __syncthreads();
    }
    if (tid == 0) out[0] = (float)(1.25 * red[0] / 8388608.0);
    __syncthreads();
    double p = (double)counts[tid] / 131072.0;
    double t = p * log(p + 1e-10);
    red[tid] = t;
    __syncthreads();
    for (int st = 256; st > 0; st >>= 1) {
        if (tid < st) red[tid] += red[tid + st];
        __syncthreads();
    }
    if (tid == 0) out[PERP_OFF] = (float)exp(-red[0]);
}

// ---------------- dec4: tconv (32,1,4) s2 p1 op1, writes recon ----------------
__global__ void dec4_kernel(const float* __restrict__ in, const float* __restrict__ wt,
                            const float* __restrict__ bias, float* __restrict__ out)
{
    int g = blockIdx.x * 256 + threadIdx.x;
    if (g >= 32*16385) return;
    int l = g % 16385;
    int b = g / 16385;
    const float4* in4 = reinterpret_cast<const float4*>(in);
    const float4* wt4 = reinterpret_cast<const float4*>(wt);
    float acc = 0.f;
    int j0 = (l + 1) & 1;
    #pragma unroll
    for (int jj = 0; jj < 2; jj++) {
        int j = j0 + 2*jj;
        int num = l + 1 - j;
        if (num >= 0) {
            int t = num >> 1;
            if (t < 8192) {
                #pragma unroll
                for (int c4 = 0; c4 < 8; c4++) {
                    float4 wv = wt4[j*8 + c4];
                    float4 xv = in4[(b*8192 + t)*8 + c4];
                    acc += wv.x*xv.x + wv.y*xv.y + wv.z*xv.z + wv.w*xv.w;
                }
            }
        }
    }
    out[1 + b*16385 + l] = acc + bias[0];
}

// ---------------- launch ----------------
extern "C" void kernel_launch(void* const* d_in, const int* in_sizes, int n_in,
                              void* d_out, int out_size)
{
    const float* x   = (const float*)d_in[0];
    const float* ew1 = (const float*)d_in[1];
    const float* eb1 = (const float*)d_in[2];
    const float* ew2 = (const float*)d_in[3];
    const float* eb2 = (const float*)d_in[4];
    const float* ew3 = (const float*)d_in[5];
    const float* eb3 = (const float*)d_in[6];
    const float* ew4 = (const float*)d_in[7];
    const float* eb4 = (const float*)d_in[8];
    const float* dw1 = (const float*)d_in[9];
    const float* db1 = (const float*)d_in[10];
    const float* dw2 = (const float*)d_in[11];
    const float* db2 = (const float*)d_in[12];
    const float* dw3 = (const float*)d_in[13];
    const float* db3 = (const float*)d_in[14];
    const float* dw4 = (const float*)d_in[15];
    const float* db4 = (const float*)d_in[16];
    const float* emb = (const float*)d_in[17];
    float* out = (float*)d_out;

    float *a2, *a3, *z, *d1, *d2, *d3;
    float *wt2, *wt3, *wt4, *wtd2, *wtd3f, *wtd4, *b3f, *partial;
    int *counts, *fidx, *flaglist, *nflag;
    cudaGetSymbolAddress((void**)&a2,    g_a2);
    cudaGetSymbolAddress((void**)&a3,    g_a3);
    cudaGetSymbolAddress((void**)&z,     g_z);
    cudaGetSymbolAddress((void**)&d1,    g_d1);
    cudaGetSymbolAddress((void**)&d2,    g_d2);
    cudaGetSymbolAddress((void**)&d3,    g_d3);
    cudaGetSymbolAddress((void**)&wt2,   g_wt2);
    cudaGetSymbolAddress((void**)&wt3,   g_wt3);
    cudaGetSymbolAddress((void**)&wt4,   g_wt4);
    cudaGetSymbolAddress((void**)&wtd2,  g_wtd2);
    cudaGetSymbolAddress((void**)&wtd3f, g_wtd3f);
    cudaGetSymbolAddress((void**)&wtd4,  g_wtd4);
    cudaGetSymbolAddress((void**)&b3f,   g_b3f);
    cudaGetSymbolAddress((void**)&partial, g_partial);
    cudaGetSymbolAddress((void**)&counts,  g_counts);
    cudaGetSymbolAddress((void**)&fidx,    g_fidx);
    cudaGetSymbolAddress((void**)&flaglist, g_flaglist);
    cudaGetSymbolAddress((void**)&nflag,    g_nflag);

    transform_kernel<<<96, 256>>>(ew2, ew3, ew4, dw2, dw3, db3, dw4,
                                  wt2, wt3, wt4, wtd2, wtd3f, b3f, wtd4);
    zero_counts_kernel<<<1, 512>>>(counts, nflag);

    // encoder — scalar fp32 (index-determining path; arithmetic identical to R6)
    enc12_kernel<<<2048, 256>>>(x, ew1, eb1, wt2, eb2, a2);
    convSs<64, 128, 3, 1, 1, true, 4, 4><<<4096, 256, 34*16*16>>>(a2, wt3, eb3, a3, 4096, 4096);
    convSs<128, 64, 1, 1, 0, false, 4, 3><<<2048, 256, 64*32*16>>>(a3, wt4, eb4, z, 4096, 4096);

    // vq — FFMA2 approx + margin screen, exact fallback, then loss/histogram
    vq_approx_kernel<<<512, 256>>>(z, emb, fidx, flaglist, nflag);
    vq_fallback_kernel<<<64, 256>>>(z, emb, flaglist, nflag, fidx);
    vq_loss_kernel<<<512, 256>>>(z, emb, fidx, out, partial, counts);
    finalize_kernel<<<1, 512>>>(partial, counts, out);

    // decoder — f32x2 packed FMA (recon tolerance 1e-3)
    convG1<64, 128><<<4096, 256, 32*16*16>>>(emb, fidx, dw1, db1, d1);
    convS2<128, 64, 3, 1, 1, true, 4><<<2048, 256, 66*32*16>>>(d1, wtd2, db2, d2, 4096, 4096);
    convS2<64, 64, 3, 1, 1, true, 4><<<2048, 256, 66*16*16>>>(d2, wtd3f, b3f, d3, 4096, 4096);
    dec4_kernel<<<2049, 256>>>(d3, wtd4, db4, out);
}

// round 8
// speedup vs baseline: 1.5131x; 1.5131x over previous
#include <cuda_runtime.h>
#include <cuda_bf16.h>
#include <math.h>

// ---------------- Problem constants ----------------
// B=32, C_IN=1, L=16384, D=64, K=512
// out: [loss(1), recon(32*16385), perplexity(1), indices(131072)] = 655394 floats

#define NROWS   131072
#define IDX_OFF 524322
#define PERP_OFF 524321

typedef unsigned long long ull;

// packed f32x2 helpers (DECODER ONLY — index path must stay scalar fp32)
#define FMA2(d,a,b,c) asm("fma.rn.f32x2 %0, %1, %2, %3;" : "=l"(d) : "l"(a), "l"(b), "l"(c))
__device__ __forceinline__ ull pk2(float v) {
    ull p; unsigned u = __float_as_uint(v);
    asm("mov.b64 %0, {%1, %1};" : "=l"(p) : "r"(u));
    return p;
}
__device__ __forceinline__ void unpk2(ull p, float& lo, float& hi) {
    unsigned a, b;
    asm("mov.b64 {%0, %1}, %2;" : "=r"(a), "=r"(b) : "l"(p));
    lo = __uint_as_float(a); hi = __uint_as_float(b);
}

// ---------------- Scratch (device globals; no allocation) ----------------
__device__ __align__(16) float g_a2[32*4096*64];
__device__ __align__(16) float g_a3[32*4096*128];
__device__ __align__(16) float g_z [NROWS*64];
__device__ __align__(16) float g_d1[32*4096*128];
__device__ __align__(16) float g_d2[32*4096*64];
__device__ __align__(16) float g_d3[32*8192*32];
__device__ __align__(16) float g_wt2[4*32*64];
__device__ __align__(16) float g_wt3[3*64*128];
__device__ __align__(16) float g_wt4[128*64];
__device__ __align__(16) float g_wtd2[3*128*64];
__device__ __align__(16) float g_wtd3f[3*64*64];
__device__ __align__(16) float g_wtd4[4*32];
__device__ __align__(16) float g_b3f[64];
__device__ float g_partial[512];
__device__ int   g_fidx[NROWS];
__device__ int   g_counts[512];

// ---------------- Weight re-layout: wt[(j*CIN+ci)*COUT + co] ----------------
__global__ void transform_kernel(const float* __restrict__ ew2, const float* __restrict__ ew3,
                                 const float* __restrict__ ew4,
                                 const float* __restrict__ dw2,
                                 const float* __restrict__ dw3, const float* __restrict__ db3,
                                 const float* __restrict__ dw4,
                                 float* __restrict__ wt2, float* __restrict__ wt3,
                                 float* __restrict__ wt4,
                                 float* __restrict__ wtd2,
                                 float* __restrict__ wtd3f, float* __restrict__ b3f,
                                 float* __restrict__ wtd4)
{
    int i = blockIdx.x * blockDim.x + threadIdx.x;
    if (i < 8192)  { int j=i/2048, ci=(i/64)%32, co=i%64;   wt2[i]  = ew2[(co*32+ci)*4 + j]; }
    if (i < 24576) { int j=i/8192, ci=(i/128)%64, co=i%128; wt3[i]  = ew3[(co*64+ci)*3 + j]; }
    if (i < 8192)  { int ci=i/64,  co=i%64;                 wt4[i]  = ew4[co*128 + ci]; }
    if (i < 24576) { int j=i/8192, ci=(i/64)%128, co=i%64;  wtd2[i] = dw2[(ci*64+co)*3 + (2-j)]; }
    if (i < 12288) {
        int j=i/4096, ci=(i/64)%64, cop=i%64;
        int phase = cop >> 5, co = cop & 31;
        int tap = -1;
        if (phase == 0) { if (j == 0) tap = 3; else if (j == 1) tap = 1; }
        else            { if (j == 1) tap = 2; else if (j == 2) tap = 0; }
        wtd3f[i] = (tap >= 0) ? dw3[(ci*32+co)*4 + tap] : 0.f;
    }
    if (i < 128)   { int j=i/32,  ci=i%32;                  wtd4[i] = dw4[ci*4 + j]; }
    if (i < 64)    { b3f[i] = db3[i & 31]; }
}

__global__ void zero_counts_kernel(int* __restrict__ counts)
{
    counts[threadIdx.x] = 0;
}

// ---------------- scalar smem-staged conv (index path — exact R4/R6 FMA chain) ----------------
template<int CIN, int COUT, int K, int S, int P, bool RELU, int TT, int MINB>
__global__ __launch_bounds__(256, MINB) void convSs(const float* __restrict__ in,
                                                    const float* __restrict__ wt,
                                                    const float* __restrict__ bias,
                                                    float* __restrict__ out,
                                                    int Lin, int Lout)
{
    constexpr int C4  = CIN / 4;
    constexpr int CO4 = COUT / 4;
    constexpr int TY  = CO4;
    constexpr int TX  = 256 / TY;
    constexpr int POS  = TX * TT;
    constexpr int PB   = (POS - 1) * S + K;
    constexpr int I4   = PB * C4;
    constexpr int SPAN = (TT - 1) * S + K;

    extern __shared__ float4 is[];
    int tid = threadIdx.x;
    int blockPos = blockIdx.x * POS;
    int b   = blockPos / Lout;
    int t0b = blockPos % Lout;
    int p0b = t0b * S - P;
    const float4* in4 = reinterpret_cast<const float4*>(in);
    for (int i = tid; i < I4; i += 256) {
        int pl = i / C4, c4 = i % C4;
        int p = p0b + pl;
        is[i] = (p >= 0 && p < Lin) ? in4[(b*Lin + p)*C4 + c4]
                                    : make_float4(0.f, 0.f, 0.f, 0.f);
    }
    __syncthreads();

    int ty = tid % TY, tx = tid / TY, tloc = tx * TT;
    const float4* wt4 = reinterpret_cast<const float4*>(wt);

    float4 acc[TT];
    #pragma unroll
    for (int tt = 0; tt < TT; tt++) acc[tt] = make_float4(0.f, 0.f, 0.f, 0.f);

    for (int c4 = 0; c4 < C4; c4++) {
        float4 iv[SPAN];
        #pragma unroll
        for (int s = 0; s < SPAN; s++) iv[s] = is[(tloc*S + s)*C4 + c4];
        #pragma unroll
        for (int j = 0; j < K; j++) {
            float4 w0 = __ldg(&wt4[(j*CIN + c4*4 + 0)*CO4 + ty]);
            float4 w1 = __ldg(&wt4[(j*CIN + c4*4 + 1)*CO4 + ty]);
            float4 w2 = __ldg(&wt4[(j*CIN + c4*4 + 2)*CO4 + ty]);
            float4 w3 = __ldg(&wt4[(j*CIN + c4*4 + 3)*CO4 + ty]);
            #pragma unroll
            for (int tt = 0; tt < TT; tt++) {
                float4 xv = iv[tt*S + j];
                acc[tt].x += w0.x*xv.x + w1.x*xv.y + w2.x*xv.z + w3.x*xv.w;
                acc[tt].y += w0.y*xv.x + w1.y*xv.y + w2.y*xv.z + w3.y*xv.w;
                acc[tt].z += w0.z*xv.x + w1.z*xv.y + w2.z*xv.z + w3.z*xv.w;
                acc[tt].w += w0.w*xv.x + w1.w*xv.y + w2.w*xv.z + w3.w*xv.w;
            }
        }
    }

    float4 bv = reinterpret_cast<const float4*>(bias)[ty];
    float4* out4 = reinterpret_cast<float4*>(out);
    #pragma unroll
    for (int tt = 0; tt < TT; tt++) {
        float4 v;
        v.x = acc[tt].x + bv.x; v.y = acc[tt].y + bv.y;
        v.z = acc[tt].z + bv.z; v.w = acc[tt].w + bv.w;
        if (RELU) {
            v.x = fmaxf(v.x, 0.f); v.y = fmaxf(v.y, 0.f);
            v.z = fmaxf(v.z, 0.f); v.w = fmaxf(v.w, 0.f);
        }
        out4[(b*Lout + t0b + tloc + tt)*CO4 + ty] = v;
    }
}

// ---------------- f32x2 smem-staged conv (DECODER ONLY) ----------------
template<int CIN, int COUT, int K, int S, int P, bool RELU, int TT>
__global__ __launch_bounds__(256) void convS2(const float* __restrict__ in,
                                              const float* __restrict__ wt,
                                              const float* __restrict__ bias,
                                              float* __restrict__ out,
                                              int Lin, int Lout)
{
    constexpr int C4  = CIN / 4;
    constexpr int CO4 = COUT / 4;
    constexpr int TY  = CO4;
    constexpr int TX  = 256 / TY;
    constexpr int POS  = TX * TT;
    constexpr int PB   = (POS - 1) * S + K;
    constexpr int I4   = PB * C4;
    constexpr int SPAN = (TT - 1) * S + K;

    extern __shared__ float4 is[];
    int tid = threadIdx.x;
    int blockPos = blockIdx.x * POS;
    int b   = blockPos / Lout;
    int t0b = blockPos % Lout;
    int p0b = t0b * S - P;
    const float4* in4 = reinterpret_cast<const float4*>(in);
    for (int i = tid; i < I4; i += 256) {
        int pl = i / C4, c4 = i % C4;
        int p = p0b + pl;
        is[i] = (p >= 0 && p < Lin) ? in4[(b*Lin + p)*C4 + c4]
                                    : make_float4(0.f, 0.f, 0.f, 0.f);
    }
    __syncthreads();

    int ty = tid % TY, tx = tid / TY, tloc = tx * TT;
    const float4* wt4 = reinterpret_cast<const float4*>(wt);

    ull a01[TT], a23[TT];
    #pragma unroll
    for (int t = 0; t < TT; t++) { a01[t] = 0ull; a23[t] = 0ull; }

    for (int c4 = 0; c4 < C4; c4++) {
        float4 iv[SPAN];
        #pragma unroll
        for (int s = 0; s < SPAN; s++) iv[s] = is[(tloc*S + s)*C4 + c4];
        #pragma unroll
        for (int j = 0; j < K; j++) {
            float4 w0 = __ldg(&wt4[(j*CIN + c4*4 + 0)*CO4 + ty]);
            float4 w1 = __ldg(&wt4[(j*CIN + c4*4 + 1)*CO4 + ty]);
            float4 w2 = __ldg(&wt4[(j*CIN + c4*4 + 2)*CO4 + ty]);
            float4 w3 = __ldg(&wt4[(j*CIN + c4*4 + 3)*CO4 + ty]);
            ulonglong2 p0 = *reinterpret_cast<ulonglong2*>(&w0);
            ulonglong2 p1 = *reinterpret_cast<ulonglong2*>(&w1);
            ulonglong2 p2 = *reinterpret_cast<ulonglong2*>(&w2);
            ulonglong2 p3 = *reinterpret_cast<ulonglong2*>(&w3);
            #pragma unroll
            for (int t = 0; t < TT; t++) {
                float4 xv = iv[t*S + j];
                ull d;
                d = pk2(xv.x); FMA2(a01[t], p0.x, d, a01[t]); FMA2(a23[t], p0.y, d, a23[t]);
                d = pk2(xv.y); FMA2(a01[t], p1.x, d, a01[t]); FMA2(a23[t], p1.y, d, a23[t]);
                d = pk2(xv.z); FMA2(a01[t], p2.x, d, a01[t]); FMA2(a23[t], p2.y, d, a23[t]);
                d = pk2(xv.w); FMA2(a01[t], p3.x, d, a01[t]); FMA2(a23[t], p3.y, d, a23[t]);
            }
        }
    }

    float4 bv = reinterpret_cast<const float4*>(bias)[ty];
    float4* out4 = reinterpret_cast<float4*>(out);
    #pragma unroll
    for (int t = 0; t < TT; t++) {
        float x0, x1, x2, x3;
        unpk2(a01[t], x0, x1);
        unpk2(a23[t], x2, x3);
        float4 v;
        v.x = x0 + bv.x; v.y = x1 + bv.y; v.z = x2 + bv.z; v.w = x3 + bv.w;
        if (RELU) {
            v.x = fmaxf(v.x, 0.f); v.y = fmaxf(v.y, 0.f);
            v.z = fmaxf(v.z, 0.f); v.w = fmaxf(v.w, 0.f);
        }
        out4[(b*Lout + t0b + tloc + t)*CO4 + ty] = v;
    }
}

// ---------------- fused enc1 + enc2 (scalar — index path) ----------------
__global__ __launch_bounds__(256) void enc12_kernel(const float* __restrict__ x,
                                                    const float* __restrict__ w1,
                                                    const float* __restrict__ b1,
                                                    const float* __restrict__ wt2,
                                                    const float* __restrict__ b2,
                                                    float* __restrict__ out)
{
    constexpr int TT = 4, TY = 16, POS = 64, PB = 130, C4 = 8, CO4 = 16, K = 4, S = 2, SPAN = 10;
    __shared__ float4 is[PB*C4];
    __shared__ float  xs[264];
    __shared__ float  w1s[128];
    __shared__ float  b1s[32];

    int tid = threadIdx.x;
    int blockPos = blockIdx.x * POS;
    int b   = blockPos >> 12;
    int t0b = blockPos & 4095;
    int p0b = t0b*2 - 1;
    int xstart = 2*p0b - 1;

    if (tid < 128) w1s[tid] = w1[tid];
    if (tid < 32)  b1s[tid] = b1[tid];
    for (int i = tid; i < 262; i += 256) {
        int xi = xstart + i;
        xs[i] = (xi >= 0 && xi < 16384) ? x[b*16384 + xi] : 0.f;
    }
    __syncthreads();

    for (int i = tid; i < PB*C4; i += 256) {
        int pl = i >> 3, c4 = i & 7;
        int pos = p0b + pl;
        float4 v = make_float4(0.f, 0.f, 0.f, 0.f);
        if (pos >= 0 && pos < 8192) {
            float r[4];
            #pragma unroll
            for (int ch = 0; ch < 4; ch++) {
                int co = c4*4 + ch;
                float acc = b1s[co];
                #pragma unroll
                for (int j = 0; j < 4; j++) acc += w1s[co*4 + j] * xs[2*pl + j];
                r[ch] = fmaxf(acc, 0.f);
            }
            v = make_float4(r[0], r[1], r[2], r[3]);
        }
        is[i] = v;
    }
    __syncthreads();

    int ty = tid % TY, tx = tid / TY, tloc = tx * TT;
    const float4* wt4 = reinterpret_cast<const float4*>(wt2);

    float4 acc[TT];
    #pragma unroll
    for (int t = 0; t < TT; t++) acc[t] = make_float4(0.f, 0.f, 0.f, 0.f);

    for (int c4 = 0; c4 < C4; c4++) {
        float4 iv[SPAN];
        #pragma unroll
        for (int s = 0; s < SPAN; s++) iv[s] = is[(tloc*S + s)*C4 + c4];
        #pragma unroll
        for (int j = 0; j < K; j++) {
            float4 w0 = __ldg(&wt4[(j*32 + c4*4 + 0)*CO4 + ty]);
            float4 w1v = __ldg(&wt4[(j*32 + c4*4 + 1)*CO4 + ty]);
            float4 w2 = __ldg(&wt4[(j*32 + c4*4 + 2)*CO4 + ty]);
            float4 w3 = __ldg(&wt4[(j*32 + c4*4 + 3)*CO4 + ty]);
            #pragma unroll
            for (int t = 0; t < TT; t++) {
                float4 xv = iv[t*S + j];
                acc[t].x += w0.x*xv.x + w1v.x*xv.y + w2.x*xv.z + w3.x*xv.w;
                acc[t].y += w0.y*xv.x + w1v.y*xv.y + w2.y*xv.z + w3.y*xv.w;
                acc[t].z += w0.z*xv.x + w1v.z*xv.y + w2.z*xv.z + w3.z*xv.w;
                acc[t].w += w0.w*xv.x + w1v.w*xv.y + w2.w*xv.z + w3.w*xv.w;
            }
        }
    }

    float4 bv = reinterpret_cast<const float4*>(b2)[ty];
    float4* out4 = reinterpret_cast<float4*>(out);
    #pragma unroll
    for (int t = 0; t < TT; t++) {
        float4 v;
        v.x = fmaxf(acc[t].x + bv.x, 0.f); v.y = fmaxf(acc[t].y + bv.y, 0.f);
        v.z = fmaxf(acc[t].z + bv.z, 0.f); v.w = fmaxf(acc[t].w + bv.w, 0.f);
        out4[(b*4096 + t0b + tloc + t)*CO4 + ty] = v;
    }
}

// ---------------- VQ: row-per-lane, chunked codes, scalar dot, 4-code ILP ----------------
// Per-code arithmetic is statement-identical to the R6 passing kernel; the only change
// is that 4 independent code chains run concurrently (pure ILP, no reassociation).
// Comparisons in ascending code order with strict < preserve lowest-index ties.
__global__ __launch_bounds__(256) void vq2_kernel(const float* __restrict__ z,
                                                  const float* __restrict__ emb,
                                                  float* __restrict__ out,
                                                  int* __restrict__ fidx,
                                                  float* __restrict__ partial,
                                                  int* __restrict__ counts)
{
    __shared__ float4 es[2048];     // 128 codes x 16 float4 = 32KB
    __shared__ float  ek2s[128];
    __shared__ float  red[256];

    int tid = threadIdx.x;
    int row = blockIdx.x * 256 + tid;
    const float4* z4 = reinterpret_cast<const float4*>(z);
    const float4* e4 = reinterpret_cast<const float4*>(emb);

    float4 zv[16];
    #pragma unroll
    for (int dv = 0; dv < 16; dv++) zv[dv] = __ldg(&z4[row*16 + dv]);

    float x2 = 0.f;
    #pragma unroll
    for (int dv = 0; dv < 16; dv++) {
        float4 v = zv[dv];
        x2 += v.x*v.x + v.y*v.y + v.z*v.z + v.w*v.w;
    }

    float best = 3.4e38f;
    int bidx = 0;
    for (int ch = 0; ch < 4; ch++) {
        for (int i = tid; i < 2048; i += 256) es[i] = e4[ch*2048 + i];
        __syncthreads();
        if (tid < 128) {
            float s = 0.f;
            #pragma unroll
            for (int dv = 0; dv < 16; dv++) {
                float4 v = es[tid*16 + dv];
                s += v.x*v.x + v.y*v.y + v.z*v.z + v.w*v.w;
            }
            ek2s[tid] = s;
        }
        __syncthreads();
        for (int c = 0; c < 128; c += 4) {
            float a0 = 0.f, a1 = 0.f, a2 = 0.f, a3 = 0.f;
            #pragma unroll
            for (int dv = 0; dv < 16; dv++) {
                float4 zd = zv[dv];
                float4 e0 = es[(c+0)*16 + dv];
                float4 e1 = es[(c+1)*16 + dv];
                float4 e2 = es[(c+2)*16 + dv];
                float4 e3 = es[(c+3)*16 + dv];
                a0 += e0.x*zd.x + e0.y*zd.y + e0.z*zd.z + e0.w*zd.w;
                a1 += e1.x*zd.x + e1.y*zd.y + e1.z*zd.z + e1.w*zd.w;
                a2 += e2.x*zd.x + e2.y*zd.y + e2.z*zd.z + e2.w*zd.w;
                a3 += e3.x*zd.x + e3.y*zd.y + e3.z*zd.z + e3.w*zd.w;
            }
            float d0 = (x2 + ek2s[c+0]) - 2.f*a0;
            float d1 = (x2 + ek2s[c+1]) - 2.f*a1;
            float d2 = (x2 + ek2s[c+2]) - 2.f*a2;
            float d3 = (x2 + ek2s[c+3]) - 2.f*a3;
            int code = ch*128 + c;
            if (d0 < best) { best = d0; bidx = code;     }
            if (d1 < best) { best = d1; bidx = code + 1; }
            if (d2 < best) { best = d2; bidx = code + 2; }
            if (d3 < best) { best = d3; bidx = code + 3; }
        }
        __syncthreads();
    }

    out[IDX_OFF + row] = (float)bidx;
    fidx[row] = bidx;
    atomicAdd(&counts[bidx], 1);

    float ls = 0.f;
    #pragma unroll
    for (int dv = 0; dv < 16; dv++) {
        float4 ev = __ldg(&e4[bidx*16 + dv]);
        float4 q = zv[dv];
        float dx = ev.x - q.x, dy = ev.y - q.y, dz = ev.z - q.z, dw = ev.w - q.w;
        ls += dx*dx + dy*dy + dz*dz + dw*dw;
    }
    red[tid] = ls;
    __syncthreads();
    for (int s = 128; s > 0; s >>= 1) {
        if (tid < s) red[tid] += red[tid + s];
        __syncthreads();
    }
    if (tid == 0) partial[blockIdx.x] = red[0];
}

// ---------------- dcv1 with gather: q = emb[fidx[row]], conv k=1 (f32x2 ok) ----------------
template<int CIN, int COUT>
__global__ __launch_bounds__(256) void convG1(const float* __restrict__ emb,
                                              const int* __restrict__ fidx,
                                              const float* __restrict__ wt,
                                              const float* __restrict__ bias,
                                              float* __restrict__ out)
{
    constexpr int C4 = CIN/4, CO4 = COUT/4, TY = CO4, TX = 256/TY, TT = 4, POS = TX*TT;
    extern __shared__ float4 is[];
    int tid = threadIdx.x;
    int blockPos = blockIdx.x * POS;
    const float4* e4 = reinterpret_cast<const float4*>(emb);
    for (int i = tid; i < POS*C4; i += 256) {
        int pl = i / C4, c4 = i % C4;
        is[i] = e4[fidx[blockPos + pl]*C4 + c4];
    }
    __syncthreads();

    int ty = tid % TY, tx = tid / TY, tloc = tx * TT;
    const float4* wt4 = reinterpret_cast<const float4*>(wt);

    ull a01[TT], a23[TT];
    #pragma unroll
    for (int t = 0; t < TT; t++) { a01[t] = 0ull; a23[t] = 0ull; }

    for (int c4 = 0; c4 < C4; c4++) {
        float4 iv[TT];
        #pragma unroll
        for (int t = 0; t < TT; t++) iv[t] = is[(tloc + t)*C4 + c4];
        float4 w0 = __ldg(&wt4[(c4*4 + 0)*CO4 + ty]);
        float4 w1 = __ldg(&wt4[(c4*4 + 1)*CO4 + ty]);
        float4 w2 = __ldg(&wt4[(c4*4 + 2)*CO4 + ty]);
        float4 w3 = __ldg(&wt4[(c4*4 + 3)*CO4 + ty]);
        ulonglong2 p0 = *reinterpret_cast<ulonglong2*>(&w0);
        ulonglong2 p1 = *reinterpret_cast<ulonglong2*>(&w1);
        ulonglong2 p2 = *reinterpret_cast<ulonglong2*>(&w2);
        ulonglong2 p3 = *reinterpret_cast<ulonglong2*>(&w3);
        #pragma unroll
        for (int t = 0; t < TT; t++) {
            float4 xv = iv[t];
            ull d;
            d = pk2(xv.x); FMA2(a01[t], p0.x, d, a01[t]); FMA2(a23[t], p0.y, d, a23[t]);
            d = pk2(xv.y); FMA2(a01[t], p1.x, d, a01[t]); FMA2(a23[t], p1.y, d, a23[t]);
            d = pk2(xv.z); FMA2(a01[t], p2.x, d, a01[t]); FMA2(a23[t], p2.y, d, a23[t]);
            d = pk2(xv.w); FMA2(a01[t], p3.x, d, a01[t]); FMA2(a23[t], p3.y, d, a23[t]);
        }
    }

    float4 bv = reinterpret_cast<const float4*>(bias)[ty];
    float4* out4 = reinterpret_cast<float4*>(out);
    #pragma unroll
    for (int t = 0; t < TT; t++) {
        float x0, x1, x2, x3;
        unpk2(a01[t], x0, x1);
        unpk2(a23[t], x2, x3);
        float4 v;
        v.x = fmaxf(x0 + bv.x, 0.f); v.y = fmaxf(x1 + bv.y, 0.f);
        v.z = fmaxf(x2 + bv.z, 0.f); v.w = fmaxf(x3 + bv.w, 0.f);
        out4[(blockPos + tloc + t)*CO4 + ty] = v;
    }
}

// ---------------- finalize: loss + perplexity ----------------
__global__ void finalize_kernel(const float* __restrict__ partial, const int* __restrict__ counts,
                                float* __restrict__ out)
{
    __shared__ double red[512];
    int tid = threadIdx.x;
    double s = 0.0;
    for (int i = tid; i < 512; i += 512) s += (double)partial[i];
    red[tid] = s;
    __syncthreads();
    for (int st = 256; st > 0; st >>= 1) {
        if (tid < st) red[tid] += red[tid + st];
        __syncthreads();
    }
    if (tid == 0) out[0] = (float)(1.25 * red[0] / 8388608.0);
    __syncthreads();
    double p = (double)counts[tid] / 131072.0;
    double t = p * log(p + 1e-10);
    red[tid] = t;
    __syncthreads();
    for (int st = 256; st > 0; st >>= 1) {
        if (tid < st) red[tid] += red[tid + st];
        __syncthreads();
    }
    if (tid == 0) out[PERP_OFF] = (float)exp(-red[0]);
}

// ---------------- dec4: tconv (32,1,4) s2 p1 op1, writes recon ----------------
__global__ void dec4_kernel(const float* __restrict__ in, const float* __restrict__ wt,
                            const float* __restrict__ bias, float* __restrict__ out)
{
    int g = blockIdx.x * 256 + threadIdx.x;
    if (g >= 32*16385) return;
    int l = g % 16385;
    int b = g / 16385;
    const float4* in4 = reinterpret_cast<const float4*>(in);
    const float4* wt4 = reinterpret_cast<const float4*>(wt);
    float acc = 0.f;
    int j0 = (l + 1) & 1;
    #pragma unroll
    for (int jj = 0; jj < 2; jj++) {
        int j = j0 + 2*jj;
        int num = l + 1 - j;
        if (num >= 0) {
            int t = num >> 1;
            if (t < 8192) {
                #pragma unroll
                for (int c4 = 0; c4 < 8; c4++) {
                    float4 wv = wt4[j*8 + c4];
                    float4 xv = in4[(b*8192 + t)*8 + c4];
                    acc += wv.x*xv.x + wv.y*xv.y + wv.z*xv.z + wv.w*xv.w;
                }
            }
        }
    }
    out[1 + b*16385 + l] = acc + bias[0];
}

// ---------------- launch ----------------
extern "C" void kernel_launch(void* const* d_in, const int* in_sizes, int n_in,
                              void* d_out, int out_size)
{
    const float* x   = (const float*)d_in[0];
    const float* ew1 = (const float*)d_in[1];
    const float* eb1 = (const float*)d_in[2];
    const float* ew2 = (const float*)d_in[3];
    const float* eb2 = (const float*)d_in[4];
    const float* ew3 = (const float*)d_in[5];
    const float* eb3 = (const float*)d_in[6];
    const float* ew4 = (const float*)d_in[7];
    const float* eb4 = (const float*)d_in[8];
    const float* dw1 = (const float*)d_in[9];
    const float* db1 = (const float*)d_in[10];
    const float* dw2 = (const float*)d_in[11];
    const float* db2 = (const float*)d_in[12];
    const float* dw3 = (const float*)d_in[13];
    const float* db3 = (const float*)d_in[14];
    const float* dw4 = (const float*)d_in[15];
    const float* db4 = (const float*)d_in[16];
    const float* emb = (const float*)d_in[17];
    float* out = (float*)d_out;

    float *a2, *a3, *z, *d1, *d2, *d3;
    float *wt2, *wt3, *wt4, *wtd2, *wtd3f, *wtd4, *b3f, *partial;
    int *counts, *fidx;
    cudaGetSymbolAddress((void**)&a2,    g_a2);
    cudaGetSymbolAddress((void**)&a3,    g_a3);
    cudaGetSymbolAddress((void**)&z,     g_z);
    cudaGetSymbolAddress((void**)&d1,    g_d1);
    cudaGetSymbolAddress((void**)&d2,    g_d2);
    cudaGetSymbolAddress((void**)&d3,    g_d3);
    cudaGetSymbolAddress((void**)&wt2,   g_wt2);
    cudaGetSymbolAddress((void**)&wt3,   g_wt3);
    cudaGetSymbolAddress((void**)&wt4,   g_wt4);
    cudaGetSymbolAddress((void**)&wtd2,  g_wtd2);
    cudaGetSymbolAddress((void**)&wtd3f, g_wtd3f);
    cudaGetSymbolAddress((void**)&wtd4,  g_wtd4);
    cudaGetSymbolAddress((void**)&b3f,   g_b3f);
    cudaGetSymbolAddress((void**)&partial, g_partial);
    cudaGetSymbolAddress((void**)&counts,  g_counts);
    cudaGetSymbolAddress((void**)&fidx,    g_fidx);

    transform_kernel<<<96, 256>>>(ew2, ew3, ew4, dw2, dw3, db3, dw4,
                                  wt2, wt3, wt4, wtd2, wtd3f, b3f, wtd4);
    zero_counts_kernel<<<1, 512>>>(counts);

    // encoder — scalar fp32 (index-determining path; arithmetic identical to R6)
    enc12_kernel<<<2048, 256>>>(x, ew1, eb1, wt2, eb2, a2);
    convSs<64, 128, 3, 1, 1, true, 4, 4><<<4096, 256, 34*16*16>>>(a2, wt3, eb3, a3, 4096, 4096);
    convSs<128, 64, 1, 1, 0, false, 4, 3><<<2048, 256, 64*32*16>>>(a3, wt4, eb4, z, 4096, 4096);

    // vq — scalar fp32 dot with 4-code ILP, lowest-index tie-break
    vq2_kernel<<<512, 256>>>(z, emb, out, fidx, partial, counts);
    finalize_kernel<<<1, 512>>>(partial, counts, out);

    // decoder — f32x2 packed FMA (recon tolerance 1e-3)
    convG1<64, 128><<<4096, 256, 32*16*16>>>(emb, fidx, dw1, db1, d1);
    convS2<128, 64, 3, 1, 1, true, 4><<<2048, 256, 66*32*16>>>(d1, wtd2, db2, d2, 4096, 4096);
    convS2<64, 64, 3, 1, 1, true, 4><<<2048, 256, 66*16*16>>>(d2, wtd3f, b3f, d3, 4096, 4096);
    dec4_kernel<<<2049, 256>>>(d3, wtd4, db4, out);
}